// round 3
// baseline (speedup 1.0000x reference)
#include <cuda_runtime.h>
#include <cstddef>

#define B_    8
#define N_    16384
#define NB    (B_ * N_)
#define L2E_  1.4426950408889634f
#define LN2_  0.6931471805599453f

// Ping-pong activation buffers (B, N, 16) fp32 — 8 MB each, both L2-resident.
__device__ float g_bufA[NB * 16];
__device__ float g_bufB[NB * 16];

static __device__ __forceinline__ float ex2f_(float x){ float y; asm("ex2.approx.f32 %0, %1;" : "=f"(y) : "f"(x)); return y; }
static __device__ __forceinline__ float rcpf_(float x){ float y; asm("rcp.approx.f32 %0, %1;" : "=f"(y) : "f"(x)); return y; }
static __device__ __forceinline__ float lg2f_(float x){ float y; asm("lg2.approx.f32 %0, %1;" : "=f"(y) : "f"(x)); return y; }

// Accurate tanh/sigmoid via ex2+rcp (rel err ~1e-6), overflow-safe.
static __device__ __forceinline__ float tanh_acc(float x){
    float e = fminf(fmaxf(-2.f * L2E_ * x, -80.f), 80.f);
    float t = ex2f_(e);
    return (1.f - t) * rcpf_(1.f + t);
}
static __device__ __forceinline__ float sig_acc(float x){
    float e = fminf(fmaxf(-L2E_ * x, -80.f), 80.f);
    return rcpf_(1.f + ex2f_(e));
}

// Packed f32x2 FMA: d = a*b + d  (SASS FFMA2 — PTX-only pattern on sm_103a)
static __device__ __forceinline__ void ffma2(float2& d, float2 a, float2 b){
    asm("fma.rn.f32x2 %0, %1, %2, %0;"
        : "+l"(*reinterpret_cast<unsigned long long*>(&d))
        : "l"(*reinterpret_cast<const unsigned long long*>(&a)),
          "l"(*reinterpret_cast<const unsigned long long*>(&b)));
}
static __device__ __forceinline__ float2 bcast2(float x){ return make_float2(x, x); }

// ---------------------------------------------------------------------------
// Layer 0: h = causal_conv(x/32768, W0, d=1) + b0 ; inp = x/32768 + h
// ---------------------------------------------------------------------------
__global__ __launch_bounds__(256) void layer0_k(
    const float* __restrict__ x, const float* __restrict__ W0,
    const float* __restrict__ b0, float* __restrict__ out)
{
    int idx = blockIdx.x * 256 + threadIdx.x;      // b*N + n
    int n = idx & (N_ - 1);
    float xc = x[idx] * (1.f / 32768.f);
    float xp = (n > 0) ? x[idx - 1] * (1.f / 32768.f) : 0.f;
    float y[16];
#pragma unroll
    for (int c = 0; c < 16; c++)
        y[c] = xc + (W0[2*c] * xp + W0[2*c + 1] * xc + b0[c]);
    float4* po = (float4*)(out + (size_t)idx * 16);
    po[0] = make_float4(y[0],  y[1],  y[2],  y[3]);
    po[1] = make_float4(y[4],  y[5],  y[6],  y[7]);
    po[2] = make_float4(y[8],  y[9],  y[10], y[11]);
    po[3] = make_float4(y[12], y[13], y[14], y[15]);
}

// ---------------------------------------------------------------------------
// Gated layer (packed f32x2):
//   f=tanh(conv_f), g=sig(conv_g), z=f*g, out=Wr@z+br, inp_next=inp+out
// One thread per (b, n). Weight smem layout fuses f and g so one broadcast
// LDS.128 feeds 2 packed FMAs:
//   wfg[k][c][op] = {Wf[2op,c,k], Wf[2op+1,c,k], Wg[2op,c,k], Wg[2op+1,c,k]}
//   wr4[c][q]     = {Wr[4q..4q+3, c]}
// ---------------------------------------------------------------------------
__global__ __launch_bounds__(128) void layer_k(
    const float* __restrict__ in, float* __restrict__ out,
    const float* __restrict__ Wf, const float* __restrict__ bf,
    const float* __restrict__ Wg, const float* __restrict__ bg,
    const float* __restrict__ Wr, const float* __restrict__ br, int d)
{
    __shared__ float4 wfg[2][16][8];     // [k][c][op]
    __shared__ float4 wr4[16][4];        // [c][q]
    __shared__ float4 sbfg[8];           // {bf[2op],bf[2op+1],bg[2op],bg[2op+1]}
    __shared__ float2 sbr2[8];

    int tid = threadIdx.x;
    // fill fused conv weights: 2*16*8 = 256 float4 entries
    for (int i = tid; i < 256; i += 128){
        int k = i >> 7, c = (i >> 3) & 15, op = i & 7;
        int o0 = 2 * op;
        wfg[k][c][op] = make_float4(Wf[(o0    ) * 32 + c * 2 + k],
                                    Wf[(o0 + 1) * 32 + c * 2 + k],
                                    Wg[(o0    ) * 32 + c * 2 + k],
                                    Wg[(o0 + 1) * 32 + c * 2 + k]);
    }
    // fill Wr packed: 16*4 float4
    for (int i = tid; i < 64; i += 128){
        int c = i >> 2, q = i & 3;
        int o0 = 4 * q;
        wr4[c][q] = make_float4(Wr[(o0    ) * 16 + c], Wr[(o0 + 1) * 16 + c],
                                Wr[(o0 + 2) * 16 + c], Wr[(o0 + 3) * 16 + c]);
    }
    if (tid < 8){
        int o0 = 2 * tid;
        sbfg[tid] = make_float4(bf[o0], bf[o0 + 1], bg[o0], bg[o0 + 1]);
        sbr2[tid] = make_float2(br[o0], br[o0 + 1]);
    }
    __syncthreads();

    int idx = blockIdx.x * 128 + tid;              // b*N + n
    int n = idx & (N_ - 1);

    float xc[16], xp[16];
    {
        const float4* pc = (const float4*)(in + (size_t)idx * 16);
        float4 v0 = pc[0], v1 = pc[1], v2 = pc[2], v3 = pc[3];
        xc[0]=v0.x; xc[1]=v0.y; xc[2]=v0.z; xc[3]=v0.w;
        xc[4]=v1.x; xc[5]=v1.y; xc[6]=v1.z; xc[7]=v1.w;
        xc[8]=v2.x; xc[9]=v2.y; xc[10]=v2.z; xc[11]=v2.w;
        xc[12]=v3.x; xc[13]=v3.y; xc[14]=v3.z; xc[15]=v3.w;
    }
    if (n >= d){
        const float4* pp = (const float4*)(in + (size_t)(idx - d) * 16);
        float4 v0 = pp[0], v1 = pp[1], v2 = pp[2], v3 = pp[3];
        xp[0]=v0.x; xp[1]=v0.y; xp[2]=v0.z; xp[3]=v0.w;
        xp[4]=v1.x; xp[5]=v1.y; xp[6]=v1.z; xp[7]=v1.w;
        xp[8]=v2.x; xp[9]=v2.y; xp[10]=v2.z; xp[11]=v2.w;
        xp[12]=v3.x; xp[13]=v3.y; xp[14]=v3.z; xp[15]=v3.w;
    } else {
#pragma unroll
        for (int c = 0; c < 16; c++) xp[c] = 0.f;
    }

    // f/g accumulation, packed over output-channel pairs
    float2 f2[8], g2[8];
#pragma unroll
    for (int op = 0; op < 8; op++){
        float4 bv = sbfg[op];
        f2[op] = make_float2(bv.x, bv.y);
        g2[op] = make_float2(bv.z, bv.w);
    }
#pragma unroll
    for (int c = 0; c < 16; c++){
        float2 xp2 = bcast2(xp[c]);
        float2 xc2 = bcast2(xc[c]);
#pragma unroll
        for (int op = 0; op < 8; op++){
            float4 w0 = wfg[0][c][op];
            ffma2(f2[op], make_float2(w0.x, w0.y), xp2);
            ffma2(g2[op], make_float2(w0.z, w0.w), xp2);
            float4 w1 = wfg[1][c][op];
            ffma2(f2[op], make_float2(w1.x, w1.y), xc2);
            ffma2(g2[op], make_float2(w1.z, w1.w), xc2);
        }
    }

    float z[16];
#pragma unroll
    for (int op = 0; op < 8; op++){
        z[2*op]   = tanh_acc(f2[op].x) * sig_acc(g2[op].x);
        z[2*op+1] = tanh_acc(f2[op].y) * sig_acc(g2[op].y);
    }

    // out = Wr@z + br ; y = xc + out   (packed over output pairs)
    float2 r2[8];
#pragma unroll
    for (int op = 0; op < 8; op++) r2[op] = sbr2[op];
#pragma unroll
    for (int c = 0; c < 16; c++){
        float2 zc2 = bcast2(z[c]);
#pragma unroll
        for (int q = 0; q < 4; q++){
            float4 w = wr4[c][q];
            ffma2(r2[2*q],     make_float2(w.x, w.y), zc2);
            ffma2(r2[2*q + 1], make_float2(w.z, w.w), zc2);
        }
    }

    float4* po = (float4*)(out + (size_t)idx * 16);
    po[0] = make_float4(xc[0]  + r2[0].x, xc[1]  + r2[0].y, xc[2]  + r2[1].x, xc[3]  + r2[1].y);
    po[1] = make_float4(xc[4]  + r2[2].x, xc[5]  + r2[2].y, xc[6]  + r2[3].x, xc[7]  + r2[3].y);
    po[2] = make_float4(xc[8]  + r2[4].x, xc[9]  + r2[4].y, xc[10] + r2[5].x, xc[11] + r2[5].y);
    po[3] = make_float4(xc[12] + r2[6].x, xc[13] + r2[6].y, xc[14] + r2[7].x, xc[15] + r2[7].y);
}

// ---------------------------------------------------------------------------
// Head: skip = relu(inp_final - x/32768); a = relu(Wa@skip + ba);
//       o = Wo@a + bo; logp = log_softmax(o); masked write (B, 256, N).
// Block = 512 threads (16 warps), tile = 64 timesteps, 4 per warp. Packed FMA.
// ---------------------------------------------------------------------------
#define HEAD_SMEM_FLOATS (16384 + 64*17 + 64*17 + 16*256 + 256*65)
#define HEAD_SMEM_BYTES  (HEAD_SMEM_FLOATS * 4)

__global__ __launch_bounds__(512) void head_k(
    const float* __restrict__ inpf, const float* __restrict__ x,
    const int* __restrict__ lengths,
    const float* __restrict__ Wa, const float* __restrict__ ba,
    const float* __restrict__ Wo, const float* __restrict__ bo,
    float* __restrict__ outp)
{
    extern __shared__ float sm[];
    float* WO = sm;                    // [64][256]  WO[k*256+o]
    float* WA = WO + 16384;            // [64][17]
    float* SK = WA + 64 * 17;          // [64][17]   relu(skip)
    float* AS = SK + 64 * 17;          // [16 warps][4 t][64]
    float* ST = AS + 16 * 256;         // [256][65]  logp staging

    int tid = threadIdx.x;
    int bId = blockIdx.x;
    int b  = bId >> 8;                 // 256 tiles of 64 per batch
    int n0 = (bId & 255) << 6;

    for (int i = tid; i < 256 * 64; i += 512){
        int o = i >> 6, k = i & 63;
        WO[k * 256 + o] = Wo[i];
    }
    for (int i = tid; i < 64 * 16; i += 512){
        int o = i >> 4, c = i & 15;
        WA[o * 17 + c] = Wa[i];
    }
    for (int i = tid; i < 64 * 16; i += 512){
        int nl = i >> 4, c = i & 15;
        float x0 = x[b * N_ + n0 + nl] * (1.f / 32768.f);
        float v = inpf[((size_t)(b * N_ + n0 + nl)) * 16 + c] - x0;
        SK[nl * 17 + c] = fmaxf(v, 0.f);
    }
    __syncthreads();

    int w = tid >> 5, l = tid & 31;

    // a = relu(Wa @ skip + ba) for this warp's 4 timesteps
#pragma unroll
    for (int t = 0; t < 4; t++){
        int nl = (w << 2) + t;
        float a0 = ba[l], a1 = ba[l + 32];
#pragma unroll
        for (int c = 0; c < 16; c++){
            float s = SK[nl * 17 + c];
            a0 += WA[l * 17 + c] * s;
            a1 += WA[(l + 32) * 17 + c] * s;
        }
        AS[w * 256 + t * 64 + l]      = fmaxf(a0, 0.f);
        AS[w * 256 + t * 64 + l + 32] = fmaxf(a1, 0.f);
    }
    __syncwarp();

    // logits: lane owns o = 4l..4l+3 (accA*) and o = 128+4l..128+4l+3 (accB*)
    float2 accA0[4], accA1[4], accB0[4], accB1[4];
    {
        float4 bA = *(const float4*)(bo + l * 4);
        float4 bB = *(const float4*)(bo + 128 + l * 4);
#pragma unroll
        for (int t = 0; t < 4; t++){
            accA0[t] = make_float2(bA.x, bA.y); accA1[t] = make_float2(bA.z, bA.w);
            accB0[t] = make_float2(bB.x, bB.y); accB1[t] = make_float2(bB.z, bB.w);
        }
    }
#pragma unroll 4
    for (int k = 0; k < 64; k++){
        float4 w0 = *(const float4*)&WO[k * 256 + l * 4];         // conflict-free
        float4 w1 = *(const float4*)&WO[k * 256 + 128 + l * 4];
        float2 w0a = make_float2(w0.x, w0.y), w0b = make_float2(w0.z, w0.w);
        float2 w1a = make_float2(w1.x, w1.y), w1b = make_float2(w1.z, w1.w);
#pragma unroll
        for (int t = 0; t < 4; t++){
            float2 av = bcast2(AS[w * 256 + t * 64 + k]);         // broadcast
            ffma2(accA0[t], w0a, av);
            ffma2(accA1[t], w0b, av);
            ffma2(accB0[t], w1a, av);
            ffma2(accB1[t], w1b, av);
        }
    }

    // per-timestep log-softmax over 256 (warp-wide), stage [o][nl]
#pragma unroll
    for (int t = 0; t < 4; t++){
        int nl = (w << 2) + t;
        float va0 = accA0[t].x, va1 = accA0[t].y, va2 = accA1[t].x, va3 = accA1[t].y;
        float vb0 = accB0[t].x, vb1 = accB0[t].y, vb2 = accB1[t].x, vb3 = accB1[t].y;
        float m = fmaxf(fmaxf(fmaxf(va0, va1), fmaxf(va2, va3)),
                        fmaxf(fmaxf(vb0, vb1), fmaxf(vb2, vb3)));
#pragma unroll
        for (int off = 16; off; off >>= 1)
            m = fmaxf(m, __shfl_xor_sync(0xffffffffu, m, off));
        float s = ex2f_((va0 - m) * L2E_) + ex2f_((va1 - m) * L2E_)
                + ex2f_((va2 - m) * L2E_) + ex2f_((va3 - m) * L2E_)
                + ex2f_((vb0 - m) * L2E_) + ex2f_((vb1 - m) * L2E_)
                + ex2f_((vb2 - m) * L2E_) + ex2f_((vb3 - m) * L2E_);
#pragma unroll
        for (int off = 16; off; off >>= 1)
            s += __shfl_xor_sync(0xffffffffu, s, off);
        float lse = lg2f_(s) * LN2_ + m;
        ST[(4 * l + 0) * 65 + nl] = va0 - lse;
        ST[(4 * l + 1) * 65 + nl] = va1 - lse;
        ST[(4 * l + 2) * 65 + nl] = va2 - lse;
        ST[(4 * l + 3) * 65 + nl] = va3 - lse;
        ST[(128 + 4 * l + 0) * 65 + nl] = vb0 - lse;
        ST[(128 + 4 * l + 1) * 65 + nl] = vb1 - lse;
        ST[(128 + 4 * l + 2) * 65 + nl] = vb2 - lse;
        ST[(128 + 4 * l + 3) * 65 + nl] = vb3 - lse;
    }
    __syncthreads();

    // coalesced masked write to (B, 256, N)
    int len = lengths[b];
    for (int i = tid; i < 256 * 64; i += 512){
        int o = i >> 6, nl = i & 63;
        int n = n0 + nl;
        float v = (n < len) ? ST[o * 65 + nl] : 0.f;
        outp[((size_t)(b * 256 + o)) * N_ + n] = v;
    }
}

// ---------------------------------------------------------------------------
extern "C" void kernel_launch(void* const* d_in, const int* in_sizes, int n_in,
                              void* d_out, int out_size)
{
    const float* x  = (const float*)d_in[0];
    const int* lengths = (const int*)d_in[1];
    const float* W0 = (const float*)d_in[2];
    const float* b0 = (const float*)d_in[3];
    const float* Wf = (const float*)d_in[4];
    const float* bf = (const float*)d_in[5];
    const float* Wg = (const float*)d_in[6];
    const float* bg = (const float*)d_in[7];
    const float* Wr = (const float*)d_in[8];
    const float* br = (const float*)d_in[9];
    const float* Wa = (const float*)d_in[10];
    const float* ba = (const float*)d_in[11];
    const float* Wo = (const float*)d_in[12];
    const float* bo = (const float*)d_in[13];
    float* out = (float*)d_out;

    float *bufA, *bufB;
    cudaGetSymbolAddress((void**)&bufA, g_bufA);
    cudaGetSymbolAddress((void**)&bufB, g_bufB);

    cudaFuncSetAttribute(head_k, cudaFuncAttributeMaxDynamicSharedMemorySize,
                         HEAD_SMEM_BYTES);

    layer0_k<<<NB / 256, 256>>>(x, W0, b0, bufA);

    float* cur = bufA;
    float* nxt = bufB;
    for (int i = 1; i < 30; i++){
        int j = i - 1;
        int d = 1 << (i % 10);
        layer_k<<<NB / 128, 128>>>(cur, nxt,
                                   Wf + j * 512, bf + j * 16,
                                   Wg + j * 512, bg + j * 16,
                                   Wr + j * 256, br + j * 16, d);
        float* tmp = cur; cur = nxt; nxt = tmp;
    }

    head_k<<<B_ * (N_ / 64), 512, HEAD_SMEM_BYTES>>>(
        cur, x, lengths, Wa, ba, Wo, bo, out);
}